// round 13
// baseline (speedup 1.0000x reference)
#include <cuda_runtime.h>
#include <cuda_bf16.h>
#include <cstdint>

#define B_  2
#define S_  2048
#define D_  1024
#define H_  16
#define HD_ 64
#define M_  (B_*S_)   // 4096

// ---------------- device scratch (allocation-free rule) ----------------
__device__ __nv_bfloat16 g_qhi[B_*H_*S_*HD_];  // [b,h,s,d] split bf16 (scale*log2e folded)
__device__ __nv_bfloat16 g_qlo[B_*H_*S_*HD_];
__device__ __nv_bfloat16 g_khi[B_*H_*S_*HD_];
__device__ __nv_bfloat16 g_klo[B_*H_*S_*HD_];
__device__ __nv_bfloat16 g_vhi[B_*H_*S_*HD_];
__device__ __nv_bfloat16 g_vlo[B_*H_*S_*HD_];
__device__ __nv_bfloat16 g_x_hi[M_*D_];        // [m][k]
__device__ __nv_bfloat16 g_x_lo[M_*D_];
__device__ __nv_bfloat16 g_att_hi[M_*D_];      // [m][n]  n = h*64+d
__device__ __nv_bfloat16 g_att_lo[M_*D_];
__device__ __nv_bfloat16 g_wt_hi[4*D_*D_];     // [n][k]
__device__ __nv_bfloat16 g_wt_lo[4*D_*D_];
__device__ float g_bias[3*D_];

// ---------------- PTX helpers (feature-free, sm_80-class) ----------------
__device__ __forceinline__ uint32_t smem_u32(const void* p) {
    uint32_t a;
    asm("{ .reg .u64 t; cvta.to.shared.u64 t, %1; cvt.u32.u64 %0, t; }" : "=r"(a) : "l"(p));
    return a;
}
__device__ __forceinline__ void cp16(uint32_t saddr, const void* g) {
    asm volatile("cp.async.cg.shared.global [%0], [%1], 16;" :: "r"(saddr), "l"(g) : "memory");
}
__device__ __forceinline__ void cp_commit() {
    asm volatile("cp.async.commit_group;" ::: "memory");
}
template <int N>
__device__ __forceinline__ void cp_wait() {
    asm volatile("cp.async.wait_group %0;" :: "n"(N) : "memory");
}
__device__ __forceinline__ void ldsm4(uint32_t& r0, uint32_t& r1, uint32_t& r2, uint32_t& r3,
                                      uint32_t a) {
    asm volatile("ldmatrix.sync.aligned.m8n8.x4.shared.b16 {%0,%1,%2,%3}, [%4];"
                 : "=r"(r0), "=r"(r1), "=r"(r2), "=r"(r3) : "r"(a));
}
__device__ __forceinline__ void ldsm4t(uint32_t& r0, uint32_t& r1, uint32_t& r2, uint32_t& r3,
                                       uint32_t a) {
    asm volatile("ldmatrix.sync.aligned.m8n8.x4.trans.shared.b16 {%0,%1,%2,%3}, [%4];"
                 : "=r"(r0), "=r"(r1), "=r"(r2), "=r"(r3) : "r"(a));
}
__device__ __forceinline__ void mma16816(float* d, const uint32_t* a, const uint32_t* b) {
    asm volatile("mma.sync.aligned.m16n8k16.row.col.f32.bf16.bf16.f32 "
                 "{%0,%1,%2,%3}, {%4,%5,%6,%7}, {%8,%9}, {%0,%1,%2,%3};"
                 : "+f"(d[0]), "+f"(d[1]), "+f"(d[2]), "+f"(d[3])
                 : "r"(a[0]), "r"(a[1]), "r"(a[2]), "r"(a[3]), "r"(b[0]), "r"(b[1]));
}
__device__ __forceinline__ uint32_t pack_hi(float a, float b) {
    __nv_bfloat162 t = __floats2bfloat162_rn(a, b);
    return *reinterpret_cast<uint32_t*>(&t);
}
__device__ __forceinline__ uint32_t pack_lo_res(float a, float b) {
    float ra = a - __bfloat162float(__float2bfloat16(a));
    float rb = b - __bfloat162float(__float2bfloat16(b));
    __nv_bfloat162 t = __floats2bfloat162_rn(ra, rb);
    return *reinterpret_cast<uint32_t*>(&t);
}

// ---------------- prep kernels ----------------
__global__ __launch_bounds__(256) void x_prep_kernel(const float* __restrict__ x) {
    int idx = blockIdx.x * 256 + threadIdx.x;
    float4 v = reinterpret_cast<const float4*>(x)[idx];
    __nv_bfloat16 h0 = __float2bfloat16(v.x), h1 = __float2bfloat16(v.y);
    __nv_bfloat16 h2 = __float2bfloat16(v.z), h3 = __float2bfloat16(v.w);
    __nv_bfloat162 hi0{h0, h1}, hi1{h2, h3};
    __nv_bfloat162 lo0{__float2bfloat16(v.x - __bfloat162float(h0)),
                       __float2bfloat16(v.y - __bfloat162float(h1))};
    __nv_bfloat162 lo1{__float2bfloat16(v.z - __bfloat162float(h2)),
                       __float2bfloat16(v.w - __bfloat162float(h3))};
    reinterpret_cast<__nv_bfloat162*>(g_x_hi)[idx * 2 + 0] = hi0;
    reinterpret_cast<__nv_bfloat162*>(g_x_hi)[idx * 2 + 1] = hi1;
    reinterpret_cast<__nv_bfloat162*>(g_x_lo)[idx * 2 + 0] = lo0;
    reinterpret_cast<__nv_bfloat162*>(g_x_lo)[idx * 2 + 1] = lo1;
}

__global__ __launch_bounds__(256) void w_prep_kernel(const float* __restrict__ Wq,
                                                     const float* __restrict__ Wk,
                                                     const float* __restrict__ Wv,
                                                     const float* __restrict__ Wo) {
    __shared__ float T[32][33];
    int z = blockIdx.z;
    const float* W = (z == 0) ? Wq : (z == 1) ? Wk : (z == 2) ? Wv : Wo;
    int k0 = blockIdx.x * 32, n0 = blockIdx.y * 32;
    int tx = threadIdx.x & 31, ty = threadIdx.x >> 5;
    #pragma unroll
    for (int i = 0; i < 4; i++)
        T[ty + 8 * i][tx] = W[(size_t)(k0 + ty + 8 * i) * D_ + n0 + tx];
    __syncthreads();
    #pragma unroll
    for (int i = 0; i < 4; i++) {
        int n = n0 + ty + 8 * i, k = k0 + tx;
        float v = T[tx][ty + 8 * i];
        __nv_bfloat16 hi = __float2bfloat16(v);
        size_t o = (size_t)(z * D_ + n) * D_ + k;
        g_wt_hi[o] = hi;
        g_wt_lo[o] = __float2bfloat16(v - __bfloat162float(hi));
    }
}

__global__ __launch_bounds__(256) void bias_prep_kernel(const float* __restrict__ bq,
                                                        const float* __restrict__ bk,
                                                        const float* __restrict__ bv) {
    int i = blockIdx.x * 256 + threadIdx.x;
    g_bias[i] = (i < D_) ? bq[i] : (i < 2 * D_) ? bk[i - D_] : bv[i - 2 * D_];
}

// ---------------- HMMA split-bf16 GEMM, fused 3-pass, 128x256 tile ----------
// 512 threads / 16 warps (wm 0..1 x wn 0..7), warp tile 64x32, BK=32.
// 3-stage cp.async pipeline, ONE __syncthreads per chunk.
// Stage layout (bytes): AH@0 10240 | AL@10240 | BH@20480 20480 | BL@40960 20480
#define NCHUNK 32
#define OFF_AL 10240u
#define OFF_BH 20480u
#define OFF_BL 40960u
#define STAGE_B 61440u
#define GSMEM (3u * STAGE_B)   // 184320

__global__ __launch_bounds__(512, 1)
void gemm_hmma_kernel(int src_mode, int b_row0,
                      const float* __restrict__ bias, float* __restrict__ outp,
                      int qkv_scatter)
{
    extern __shared__ char smg[];
    const uint32_t s0 = smem_u32(smg);

    const int tid = threadIdx.x;
    const int wid = tid >> 5;
    const int lane = tid & 31;
    const int m0 = blockIdx.y * 128;
    const int n0 = blockIdx.x * 256;
    const int wm = wid & 1;
    const int wn = wid >> 1;

    const __nv_bfloat16* a_hi = src_mode ? g_att_hi : g_x_hi;
    const __nv_bfloat16* a_lo = src_mode ? g_att_lo : g_x_lo;

    float acc[4][4][4];
    #pragma unroll
    for (int i = 0; i < 4; i++)
        #pragma unroll
        for (int j = 0; j < 4; j++)
            acc[i][j][0] = acc[i][j][1] = acc[i][j][2] = acc[i][j][3] = 0.f;

    const int lrow = tid >> 2;      // 0..127
    const int seg  = tid & 3;

    auto issue_load = [&](int c, int st) {
        const int k0 = c * 32;
        const uint32_t sb = s0 + st * STAGE_B;
        const uint32_t so = (uint32_t)(lrow * 80 + seg * 16);
        const size_t goA = (size_t)(m0 + lrow) * D_ + k0 + seg * 8;
        cp16(sb + so,          a_hi + goA);
        cp16(sb + OFF_AL + so, a_lo + goA);
        const size_t goB = (size_t)(b_row0 + n0 + lrow) * D_ + k0 + seg * 8;
        cp16(sb + OFF_BH + so, g_wt_hi + goB);
        cp16(sb + OFF_BL + so, g_wt_lo + goB);
        const size_t goB2 = goB + (size_t)128 * D_;
        cp16(sb + OFF_BH + so + 128u * 80u, g_wt_hi + goB2);
        cp16(sb + OFF_BL + so + 128u * 80u, g_wt_lo + goB2);
        cp_commit();
    };

    issue_load(0, 0);
    issue_load(1, 1);

    int st = 0;
    for (int c = 0; c < NCHUNK; ++c) {
        if (c + 1 < NCHUNK) cp_wait<1>(); else cp_wait<0>();
        __syncthreads();
        if (c + 2 < NCHUNK) issue_load(c + 2, (st + 2 >= 3) ? st - 1 : st + 2);

        const uint32_t aHB = s0 + st * STAGE_B;
        const uint32_t aLB = aHB + OFF_AL;
        const uint32_t bHB = aHB + OFF_BH;
        const uint32_t bLB = aHB + OFF_BL;

        #pragma unroll
        for (int kk = 0; kk < 2; ++kk) {
            const uint32_t a_off = (uint32_t)((wm * 64 + (lane & 15)) * 80 +
                                              (kk * 2 + (lane >> 4)) * 16);
            const int bg   = lane >> 3;
            const uint32_t b_off0 = (uint32_t)((wn * 32 + ((bg & 2) ? 8 : 0) + (lane & 7)) * 80 +
                                               (kk * 2 + (bg & 1)) * 16);

            uint32_t afh[4][4], bfh[4][2];
            #pragma unroll
            for (int mt = 0; mt < 4; ++mt)
                ldsm4(afh[mt][0], afh[mt][1], afh[mt][2], afh[mt][3],
                      aHB + a_off + (uint32_t)mt * 16 * 80);
            #pragma unroll
            for (int j = 0; j < 2; ++j) {
                uint32_t r0, r1, r2, r3;
                ldsm4(r0, r1, r2, r3, bHB + b_off0 + (uint32_t)j * 16 * 80);
                bfh[j * 2 + 0][0] = r0; bfh[j * 2 + 0][1] = r1;
                bfh[j * 2 + 1][0] = r2; bfh[j * 2 + 1][1] = r3;
            }
            // pass 1: hi * hi
            #pragma unroll
            for (int mt = 0; mt < 4; ++mt)
                #pragma unroll
                for (int nt = 0; nt < 4; ++nt)
                    mma16816(acc[mt][nt], afh[mt], bfh[nt]);
            // pass 2: hi * lo  (reuse afh)
            {
                uint32_t bfl[4][2];
                #pragma unroll
                for (int j = 0; j < 2; ++j) {
                    uint32_t r0, r1, r2, r3;
                    ldsm4(r0, r1, r2, r3, bLB + b_off0 + (uint32_t)j * 16 * 80);
                    bfl[j * 2 + 0][0] = r0; bfl[j * 2 + 0][1] = r1;
                    bfl[j * 2 + 1][0] = r2; bfl[j * 2 + 1][1] = r3;
                }
                #pragma unroll
                for (int mt = 0; mt < 4; ++mt)
                    #pragma unroll
                    for (int nt = 0; nt < 4; ++nt)
                        mma16816(acc[mt][nt], afh[mt], bfl[nt]);
            }
            // pass 3: lo * hi  (reuse bfh)
            {
                uint32_t afl[4][4];
                #pragma unroll
                for (int mt = 0; mt < 4; ++mt)
                    ldsm4(afl[mt][0], afl[mt][1], afl[mt][2], afl[mt][3],
                          aLB + a_off + (uint32_t)mt * 16 * 80);
                #pragma unroll
                for (int mt = 0; mt < 4; ++mt)
                    #pragma unroll
                    for (int nt = 0; nt < 4; ++nt)
                        mma16816(acc[mt][nt], afl[mt], bfh[nt]);
            }
        }
        st = (st + 1 >= 3) ? 0 : st + 1;
    }

    // ---- epilogue ----
    #pragma unroll
    for (int nt = 0; nt < 4; ++nt) {
        int ng = n0 + wn * 32 + nt * 8 + (lane & 3) * 2;
        float bx = bias[ng], by = bias[ng + 1];
        if (qkv_scatter) {
            int sel = ng >> 10;
            int nl  = ng & (D_ - 1);
            int hh  = nl >> 6;
            int dd  = nl & 63;
            float scale = (sel == 0) ? 0.125f * 1.44269504089f : 1.0f;
            __nv_bfloat16* dh = (sel == 0) ? g_qhi : (sel == 1) ? g_khi : g_vhi;
            __nv_bfloat16* dl = (sel == 0) ? g_qlo : (sel == 1) ? g_klo : g_vlo;
            #pragma unroll
            for (int mt = 0; mt < 4; ++mt) {
                #pragma unroll
                for (int h2 = 0; h2 < 2; ++h2) {
                    int row = m0 + wm * 64 + mt * 16 + (lane >> 2) + h2 * 8;
                    int bb = row >> 11, ss = row & (S_ - 1);
                    float vx = (acc[mt][nt][h2 * 2 + 0] + bx) * scale;
                    float vy = (acc[mt][nt][h2 * 2 + 1] + by) * scale;
                    size_t idx = (((size_t)bb * H_ + hh) * S_ + ss) * HD_ + dd;
                    *reinterpret_cast<uint32_t*>(dh + idx) = pack_hi(vx, vy);
                    *reinterpret_cast<uint32_t*>(dl + idx) = pack_lo_res(vx, vy);
                }
            }
        } else {
            #pragma unroll
            for (int mt = 0; mt < 4; ++mt) {
                #pragma unroll
                for (int h2 = 0; h2 < 2; ++h2) {
                    int row = m0 + wm * 64 + mt * 16 + (lane >> 2) + h2 * 8;
                    float2 v;
                    v.x = acc[mt][nt][h2 * 2 + 0] + bx;
                    v.y = acc[mt][nt][h2 * 2 + 1] + by;
                    *reinterpret_cast<float2*>(outp + (size_t)row * D_ + ng) = v;
                }
            }
        }
    }
}

// ---------------------------------------------------------------------------
// HMMA flash attention, fused-pass (unchanged from R12).
// ---------------------------------------------------------------------------
#define ATT_SMEM 110592

__global__ __launch_bounds__(256, 2)
void attn_hmma_kernel()
{
    extern __shared__ char smc[];
    const uint32_t sb = smem_u32(smc);
    const int tid  = threadIdx.x;
    const int lane = tid & 31;
    const int wid  = tid >> 5;
    const int q0   = wid * 16;
    const int qt = blockIdx.x, h = blockIdx.y, b = blockIdx.z;

    const __nv_bfloat16* gqh = g_qhi + (((size_t)b * H_ + h) * S_ + qt * 128) * HD_;
    const __nv_bfloat16* gql = g_qlo + (((size_t)b * H_ + h) * S_ + qt * 128) * HD_;
    const __nv_bfloat16* gkh = g_khi + ((size_t)b * H_ + h) * S_ * HD_;
    const __nv_bfloat16* gkl = g_klo + ((size_t)b * H_ + h) * S_ * HD_;
    const __nv_bfloat16* gvh = g_vhi + ((size_t)b * H_ + h) * S_ * HD_;
    const __nv_bfloat16* gvl = g_vlo + ((size_t)b * H_ + h) * S_ * HD_;

    {
        int r  = tid >> 1;
        int s4 = (tid & 1) * 4;
        const __nv_bfloat16* sh = gqh + (size_t)r * HD_ + s4 * 8;
        const __nv_bfloat16* sl = gql + (size_t)r * HD_ + s4 * 8;
        uint32_t dh = sb + r * 144 + s4 * 16;
        uint32_t dl = sb + 18432 + r * 144 + s4 * 16;
        #pragma unroll
        for (int i = 0; i < 4; i++) {
            cp16(dh + i * 16, sh + i * 8);
            cp16(dl + i * 16, sl + i * 8);
        }
        cp_commit();
    }

    auto issue_kv = [&](int c, int st) {
        int r  = tid >> 2;
        int sg = (tid & 3) * 2;
        size_t go = (size_t)(c * 64 + r) * HD_ + sg * 8;
        uint32_t sd = sb + 36864 + st * 36864 + r * 144 + sg * 16;
        cp16(sd,              gkh + go); cp16(sd + 16,              gkh + go + 8);
        cp16(sd + 9216,       gkl + go); cp16(sd + 9216 + 16,       gkl + go + 8);
        cp16(sd + 18432,      gvh + go); cp16(sd + 18432 + 16,      gvh + go + 8);
        cp16(sd + 27648,      gvl + go); cp16(sd + 27648 + 16,      gvl + go + 8);
        cp_commit();
    };

    issue_kv(0, 0);

    float o[8][4];
    #pragma unroll
    for (int n = 0; n < 8; n++)
        o[n][0] = o[n][1] = o[n][2] = o[n][3] = 0.f;
    float mA = -1e30f, mB = -1e30f, lA = 0.f, lB = 0.f;

    const uint32_t qhb = sb, qlb = sb + 18432;
    const uint32_t a_row_off = (uint32_t)(q0 + (lane & 15)) * 144 + (lane >> 4) * 16;
    const uint32_t k_row_off = (uint32_t)(lane & 15) * 144 + (lane >> 4) * 16;

    for (int c = 0; c < S_ / 64; ++c) {
        const int st = c & 1;
        if (c + 1 < S_ / 64) {
            issue_kv(c + 1, st ^ 1);
            cp_wait<1>();
        } else {
            cp_wait<0>();
        }
        __syncthreads();

        const uint32_t kbh = sb + 36864 + st * 36864;
        const uint32_t kbl = kbh + 9216;
        const uint32_t vbh = kbh + 18432;
        const uint32_t vbl = kbh + 27648;

        float s[8][4];
        #pragma unroll
        for (int n = 0; n < 8; n++)
            s[n][0] = s[n][1] = s[n][2] = s[n][3] = 0.f;

        #pragma unroll
        for (int kk = 0; kk < 4; kk++) {
            uint32_t ah[4], al[4];
            ldsm4(ah[0], ah[1], ah[2], ah[3], qhb + a_row_off + kk * 32);
            ldsm4(al[0], al[1], al[2], al[3], qlb + a_row_off + kk * 32);
            #pragma unroll
            for (int g = 0; g < 4; g++) {
                uint32_t r0, r1, r2, r3;
                ldsm4(r0, r1, r2, r3, kbh + k_row_off + (uint32_t)g * 16 * 144 + kk * 32);
                uint32_t bh0[2] = {r0, r2}, bh1[2] = {r1, r3};
                mma16816(s[2 * g],     ah, bh0);
                mma16816(s[2 * g + 1], ah, bh1);
                mma16816(s[2 * g],     al, bh0);
                mma16816(s[2 * g + 1], al, bh1);
                ldsm4(r0, r1, r2, r3, kbl + k_row_off + (uint32_t)g * 16 * 144 + kk * 32);
                uint32_t bl0[2] = {r0, r2}, bl1[2] = {r1, r3};
                mma16816(s[2 * g],     ah, bl0);
                mma16816(s[2 * g + 1], ah, bl1);
            }
        }

        float mxA = -1e30f, mxB = -1e30f;
        #pragma unroll
        for (int n = 0; n < 8; n++) {
            mxA = fmaxf(mxA, fmaxf(s[n][0], s[n][1]));
            mxB = fmaxf(mxB, fmaxf(s[n][2], s[n][3]));
        }
        mxA = fmaxf(mxA, __shfl_xor_sync(0xffffffffu, mxA, 1));
        mxA = fmaxf(mxA, __shfl_xor_sync(0xffffffffu, mxA, 2));
        mxB = fmaxf(mxB, __shfl_xor_sync(0xffffffffu, mxB, 1));
        mxB = fmaxf(mxB, __shfl_xor_sync(0xffffffffu, mxB, 2));
        float mnA = fmaxf(mA, mxA), mnB = fmaxf(mB, mxB);
        float cA = exp2f(mA - mnA), cB = exp2f(mB - mnB);
        float psA = 0.f, psB = 0.f;
        #pragma unroll
        for (int n = 0; n < 8; n++) {
            s[n][0] = exp2f(s[n][0] - mnA); psA += s[n][0];
            s[n][1] = exp2f(s[n][1] - mnA); psA += s[n][1];
            s[n][2] = exp2f(s[n][2] - mnB); psB += s[n][2];
            s[n][3] = exp2f(s[n][3] - mnB); psB += s[n][3];
        }
        psA += __shfl_xor_sync(0xffffffffu, psA, 1);
        psA += __shfl_xor_sync(0xffffffffu, psA, 2);
        psB += __shfl_xor_sync(0xffffffffu, psB, 1);
        psB += __shfl_xor_sync(0xffffffffu, psB, 2);
        lA = lA * cA + psA; lB = lB * cB + psB;
        mA = mnA; mB = mnB;
        #pragma unroll
        for (int n = 0; n < 8; n++) {
            o[n][0] *= cA; o[n][1] *= cA; o[n][2] *= cB; o[n][3] *= cB;
        }

        #pragma unroll
        for (int kk = 0; kk < 4; kk++) {
            uint32_t phi[4], pl[4];
            phi[0] = pack_hi(s[2 * kk][0],     s[2 * kk][1]);
            phi[1] = pack_hi(s[2 * kk][2],     s[2 * kk][3]);
            phi[2] = pack_hi(s[2 * kk + 1][0], s[2 * kk + 1][1]);
            phi[3] = pack_hi(s[2 * kk + 1][2], s[2 * kk + 1][3]);
            pl[0] = pack_lo_res(s[2 * kk][0],     s[2 * kk][1]);
            pl[1] = pack_lo_res(s[2 * kk][2],     s[2 * kk][3]);
            pl[2] = pack_lo_res(s[2 * kk + 1][0], s[2 * kk + 1][1]);
            pl[3] = pack_lo_res(s[2 * kk + 1][2], s[2 * kk + 1][3]);
            #pragma unroll
            for (int g = 0; g < 4; g++) {
                uint32_t r0, r1, r2, r3;
                ldsm4t(r0, r1, r2, r3,
                       vbh + k_row_off + (uint32_t)kk * 16 * 144 + g * 32);
                uint32_t bh0[2] = {r0, r1}, bh1[2] = {r2, r3};
                mma16816(o[2 * g],     phi, bh0);
                mma16816(o[2 * g + 1], phi, bh1);
                mma16816(o[2 * g],     pl,  bh0);
                mma16816(o[2 * g + 1], pl,  bh1);
                ldsm4t(r0, r1, r2, r3,
                       vbl + k_row_off + (uint32_t)kk * 16 * 144 + g * 32);
                uint32_t bl0[2] = {r0, r1}, bl1[2] = {r2, r3};
                mma16816(o[2 * g],     phi, bl0);
                mma16816(o[2 * g + 1], phi, bl1);
            }
        }
        __syncthreads();
    }

    float invA = 1.f / lA, invB = 1.f / lB;
    int rowA = qt * 128 + q0 + (lane >> 2);
    int rowB = rowA + 8;
    size_t baseA = ((size_t)b * S_ + rowA) * D_ + h * HD_ + (lane & 3) * 2;
    size_t baseB = ((size_t)b * S_ + rowB) * D_ + h * HD_ + (lane & 3) * 2;
    #pragma unroll
    for (int n = 0; n < 8; n++) {
        float ax = o[n][0] * invA, ay = o[n][1] * invA;
        float bx = o[n][2] * invB, by = o[n][3] * invB;
        *reinterpret_cast<uint32_t*>(g_att_hi + baseA + n * 8) = pack_hi(ax, ay);
        *reinterpret_cast<uint32_t*>(g_att_lo + baseA + n * 8) = pack_lo_res(ax, ay);
        *reinterpret_cast<uint32_t*>(g_att_hi + baseB + n * 8) = pack_hi(bx, by);
        *reinterpret_cast<uint32_t*>(g_att_lo + baseB + n * 8) = pack_lo_res(bx, by);
    }
}

// ---------------------------------------------------------------------------
extern "C" void kernel_launch(void* const* d_in, const int* in_sizes, int n_in,
                              void* d_out, int out_size)
{
    const float* x  = (const float*)d_in[0];
    const float* Wq = (const float*)d_in[1];
    const float* bq = (const float*)d_in[2];
    const float* Wk = (const float*)d_in[3];
    const float* bk = (const float*)d_in[4];
    const float* Wv = (const float*)d_in[5];
    const float* bv = (const float*)d_in[6];
    const float* Wo = (const float*)d_in[7];
    const float* bo = (const float*)d_in[8];
    float* out = (float*)d_out;

    cudaFuncSetAttribute(attn_hmma_kernel, cudaFuncAttributeMaxDynamicSharedMemorySize, ATT_SMEM);
    cudaFuncSetAttribute(gemm_hmma_kernel, cudaFuncAttributeMaxDynamicSharedMemorySize, (int)GSMEM);

    // prep
    x_prep_kernel<<<M_ * D_ / 4 / 256, 256>>>(x);
    dim3 wgrid(D_ / 32, D_ / 32, 4);
    w_prep_kernel<<<wgrid, 256>>>(Wq, Wk, Wv, Wo);
    bias_prep_kernel<<<3 * D_ / 256, 256>>>(bq, bk, bv);

    // QKV projection: C[4096 x 3072] -> split bf16 q/k/v (head-major)
    dim3 qkv_grid(3 * D_ / 256, M_ / 128);
    gemm_hmma_kernel<<<qkv_grid, 512, GSMEM>>>(0, 0, g_bias, nullptr, 1);

    // attention
    dim3 attn_grid(S_ / 128, H_, B_);
    attn_hmma_kernel<<<attn_grid, 256, ATT_SMEM>>>();

    // output projection: C[4096 x 1024]
    dim3 out_grid(D_ / 256, M_ / 128);
    gemm_hmma_kernel<<<out_grid, 512, GSMEM>>>(1, 3 * D_, bo, out, 0);
}